// round 2
// baseline (speedup 1.0000x reference)
#include <cuda_runtime.h>
#include <cuda_bf16.h>
#include <cstdint>

// x: [4,16,4096,16] f32 -> out: [4,16,4096,273] f32
//   out[..., 0]      = 1
//   out[..., 1:17]   = x * 0.5                      (1/RRD, RRD = (16)^(1/4) = 2)
//   out[..., 17:273] = outer(x,x).flatten * 1/(sqrt(2)*4)
//
// Strategy: HBM-write-bound (286 MB out vs 16 MB in). One block = 32 rows.
// Stage 32x16 inputs in smem, then emit 8736 contiguous floats per block as
// float4 streaming stores. 32*273 = 8736 ≡ 0 (mod 4) keeps every block's
// region 16B-aligned.

#define ROWS_PER_BLOCK 32
#define D 16
#define FEAT 273                       // 1 + 16 + 256
#define BLOCK_FLOATS (ROWS_PER_BLOCK * FEAT)   // 8736
#define BLOCK_VEC4 (BLOCK_FLOATS / 4)          // 2184
#define THREADS 256

__global__ __launch_bounds__(THREADS) void taylor_exp_kernel(
    const float* __restrict__ x, float* __restrict__ out)
{
    __shared__ float sx[ROWS_PER_BLOCK][D];

    const int tid = threadIdx.x;
    const long long block_row0 = (long long)blockIdx.x * ROWS_PER_BLOCK;

    // Stage input: 32 rows * 16 floats = 512 floats = 128 float4, contiguous.
    {
        const float4* xin = reinterpret_cast<const float4*>(x + block_row0 * D);
        if (tid < (ROWS_PER_BLOCK * D / 4)) {
            float4 v = __ldg(&xin[tid]);
            float* dst = &sx[0][0] + tid * 4;
            dst[0] = v.x; dst[1] = v.y; dst[2] = v.z; dst[3] = v.w;
        }
    }
    __syncthreads();

    const float inv_rrd = 0.5f;                    // 1/RRD
    const float inv_sc  = 0.17677669529663687f;    // 1/(sqrt(2)*sqrt(16))

    float4* obase = reinterpret_cast<float4*>(out + block_row0 * FEAT);

    #pragma unroll
    for (int it = 0; it < (BLOCK_VEC4 + THREADS - 1) / THREADS; ++it) {
        int v4 = it * THREADS + tid;
        if (v4 < BLOCK_VEC4) {
            int e0 = v4 * 4;
            float4 v;
            float* vp = reinterpret_cast<float*>(&v);
            #pragma unroll
            for (int c = 0; c < 4; ++c) {
                int e = e0 + c;
                int row = e / FEAT;           // magic-mul division
                int f = e - row * FEAT;
                float val;
                if (f == 0) {
                    val = 1.0f;
                } else if (f < 17) {
                    val = sx[row][f - 1] * inv_rrd;
                } else {
                    int k = f - 17;
                    val = sx[row][k >> 4] * sx[row][k & 15] * inv_sc;
                }
                vp[c] = val;
            }
            // streaming store: output (286 MB) >> L2, skip allocate
            __stcs(&obase[v4], v);
        }
    }
}

extern "C" void kernel_launch(void* const* d_in, const int* in_sizes, int n_in,
                              void* d_out, int out_size)
{
    const float* x = (const float*)d_in[0];
    float* out = (float*)d_out;

    int n_rows = in_sizes[0] / D;          // 262144
    int n_blocks = n_rows / ROWS_PER_BLOCK; // 8192

    taylor_exp_kernel<<<n_blocks, THREADS>>>(x, out);
}

// round 3
// speedup vs baseline: 1.6196x; 1.6196x over previous
#include <cuda_runtime.h>
#include <cuda_bf16.h>
#include <cstdint>

// x: [4,16,4096,16] f32 -> out: [4,16,4096,273] f32
//   out[..., 0]      = 1
//   out[..., 1:17]   = x * 0.5
//   out[..., 17:273] = outer(x,x).flatten * 0.17677669529663687
//
// R2 found the kernel issue-bound (~32 instr/elem from per-element div-by-273
// + predicated 3-way branch). Rework:
//  - Uniform compute: every output element = s_op[A] * s_op[B] (smem reads).
//    s_op per row = {1.0, x*0.5 x16, 1.0, x*sqrt(s) x16}; quadratic terms use
//    (x_i*sqrt(s))*(x_j*sqrt(s)) = x_i*x_j*s.
//  - lcm(273,4)=1092 elems = 4 rows: decode repeats with period 1092 and no
//    float4 crosses a period boundary. A 1092-entry smem table packs the two
//    operand byte-offsets (within a 4-row operand slab) per element.
//  - Main loop per float4: 1 magic div, 1 LDS.128 table read, 4x(unpack+2 LDS
//    + FMUL), 1 STG.128 streaming store.

#define D 16
#define FEAT 273
#define ROWS_PER_BLOCK 32
#define BLOCK_FLOATS (ROWS_PER_BLOCK * FEAT)   // 8736
#define BLOCK_VEC4   (BLOCK_FLOATS / 4)        // 2184
#define THREADS 256
#define PERIOD 1092                            // 4 rows * 273
#define OPSTRIDE 36                            // floats per row in s_op (34 used)
#define SLABBYTES (4 * OPSTRIDE * 4)           // bytes per 4-row operand slab = 576

__global__ __launch_bounds__(THREADS) void taylor_exp_kernel(
    const float* __restrict__ x, float* __restrict__ out)
{
    __shared__ float    s_op[ROWS_PER_BLOCK * OPSTRIDE];   // 4608 B
    __shared__ unsigned s_tbl[PERIOD];                     // 4368 B

    const int tid = threadIdx.x;
    const long long block_row0 = (long long)blockIdx.x * ROWS_PER_BLOCK;

    const float LIN = 0.5f;                       // 1/RRD
    const float SQS = 0.42044820762685725f;       // sqrt(1/(sqrt(2)*4))

    // ---- stage operands: 32 rows x 16 floats via 128 float4 loads ----
    if (tid < (ROWS_PER_BLOCK * D / 4)) {
        const float4* xin = reinterpret_cast<const float4*>(x + block_row0 * D);
        float4 v = __ldg(&xin[tid]);
        int row = tid >> 2;
        int q   = (tid & 3) * 4;
        float* r = &s_op[row * OPSTRIDE];
        r[1 + q + 0]  = v.x * LIN;  r[1 + q + 1]  = v.y * LIN;
        r[1 + q + 2]  = v.z * LIN;  r[1 + q + 3]  = v.w * LIN;
        r[18 + q + 0] = v.x * SQS;  r[18 + q + 1] = v.y * SQS;
        r[18 + q + 2] = v.z * SQS;  r[18 + q + 3] = v.w * SQS;
    }
    if (tid < ROWS_PER_BLOCK) {
        s_op[tid * OPSTRIDE + 0]  = 1.0f;   // constant operand
        s_op[tid * OPSTRIDE + 17] = 1.0f;   // unit B-operand for prefix
    }

    // ---- build decode table (same for every block; cheap, ~4 iters) ----
    #pragma unroll
    for (int idx = tid; idx < PERIOD; idx += THREADS) {
        int r = (idx >= 273) + (idx >= 546) + (idx >= 819);   // row within group
        int f = idx - 273 * r;
        int a, b;
        if (f == 0)       { a = 0;  b = 17; }
        else if (f < 17)  { a = f;  b = 17; }
        else { int k = f - 17; a = 18 + (k >> 4); b = 18 + (k & 15); }
        unsigned offA = (unsigned)((r * OPSTRIDE + a) * 4);   // byte offsets
        unsigned offB = (unsigned)((r * OPSTRIDE + b) * 4);
        s_tbl[idx] = (offA << 16) | offB;
    }
    __syncthreads();

    // ---- main loop: block-linear float4 output ----
    const char* opc = reinterpret_cast<const char*>(s_op);
    float4* obase = reinterpret_cast<float4*>(out + block_row0 * FEAT);

    #pragma unroll
    for (int it = 0; it < (BLOCK_VEC4 + THREADS - 1) / THREADS; ++it) {
        int v4 = it * THREADS + tid;
        if (v4 < BLOCK_VEC4) {
            int g  = v4 / 273;                  // 4-row group (magic mul)
            int m0 = (v4 - g * 273) * 4;        // element index within period
            uint4 tt = *reinterpret_cast<const uint4*>(&s_tbl[m0]);
            const char* base = opc + g * SLABBYTES;
            float4 o;
            o.x = *reinterpret_cast<const float*>(base + (tt.x >> 16)) *
                  *reinterpret_cast<const float*>(base + (tt.x & 0xFFFFu));
            o.y = *reinterpret_cast<const float*>(base + (tt.y >> 16)) *
                  *reinterpret_cast<const float*>(base + (tt.y & 0xFFFFu));
            o.z = *reinterpret_cast<const float*>(base + (tt.z >> 16)) *
                  *reinterpret_cast<const float*>(base + (tt.z & 0xFFFFu));
            o.w = *reinterpret_cast<const float*>(base + (tt.w >> 16)) *
                  *reinterpret_cast<const float*>(base + (tt.w & 0xFFFFu));
            __stcs(&obase[v4], o);              // streaming: output >> L2
        }
    }
}

extern "C" void kernel_launch(void* const* d_in, const int* in_sizes, int n_in,
                              void* d_out, int out_size)
{
    const float* x = (const float*)d_in[0];
    float* out = (float*)d_out;

    int n_rows = in_sizes[0] / D;               // 262144
    int n_blocks = n_rows / ROWS_PER_BLOCK;     // 8192

    taylor_exp_kernel<<<n_blocks, THREADS>>>(x, out);
}